// round 9
// baseline (speedup 1.0000x reference)
#include <cuda_runtime.h>

#define IN_F   4096
#define OUT_F  4096
#define BATCH  16384

#define NCHUNK     4
#define CHUNK_COLS 1024               // columns per chunk
#define CHUNK_CG   (CHUNK_COLS / 4)   // 256 float4 groups per chunk
#define NSPLIT_C   256                // row-splits per chunk for W partials
#define ROWS_PER_SPLIT (OUT_F / NSPLIT_C)  // 16

// Scratch (no device allocation allowed) — fully overwritten every launch
// sequence, so graph replays are deterministic.
__device__ float g_partial[NCHUNK * NSPLIT_C * CHUNK_COLS];  // 4 MB
__device__ float g_ws[IN_F];
__device__ float g_bsum;

// ---------------------------------------------------------------------------
// A1 (per chunk): partial column sums of W over columns [chunk*1024, +1024).
// tid -> (split, colgroup). Coalesced float4 row reads. 65536 threads
// (256 blocks x 256), 16 rows each, unroll 4 (MLP_p1 cap per R6 finding).
// ---------------------------------------------------------------------------
__global__ __launch_bounds__(256)
void wsum_partial_chunk(const float4* __restrict__ W4, int chunk) {
    const int rowcg = IN_F / 4;                       // 1024 float4 per W row
    int tid   = blockIdx.x * blockDim.x + threadIdx.x;
    int colg  = tid & (CHUNK_CG - 1);                 // 0..255
    int split = tid >> 8;                             // 0..255
    const float4* p = W4 + (size_t)(split * ROWS_PER_SPLIT) * rowcg
                         + chunk * CHUNK_CG + colg;

    float4 acc = make_float4(0.f, 0.f, 0.f, 0.f);
    #pragma unroll 4
    for (int r = 0; r < ROWS_PER_SPLIT; ++r) {
        float4 v = p[(size_t)r * rowcg];
        acc.x += v.x; acc.y += v.y; acc.z += v.z; acc.w += v.w;
    }
    reinterpret_cast<float4*>(g_partial)[(chunk * NSPLIT_C + split) * CHUNK_CG + colg] = acc;
}

// ---------------------------------------------------------------------------
// A2 (per chunk): finalize ws for this chunk. 32 blocks x 256.
// Block b owns chunk-columns b*32..b*32+31; group g (tid>>5) sums splits
// [g*32, g*32+32), cross-group reduce in smem (fixed order -> deterministic).
// On the LAST chunk, block 0 also reduces bias -> g_bsum.
// ---------------------------------------------------------------------------
__global__ __launch_bounds__(256)
void wsum_finalize_chunk(const float* __restrict__ bias, int chunk) {
    __shared__ float sh[256];
    int lane = threadIdx.x & 31;
    int g    = threadIdx.x >> 5;                      // 0..7
    int jj   = blockIdx.x * 32 + lane;                // chunk-column 0..1023

    float s = 0.f;
    #pragma unroll 8
    for (int k = g * 32; k < g * 32 + 32; ++k)
        s += g_partial[(chunk * NSPLIT_C + k) * CHUNK_COLS + jj];
    sh[threadIdx.x] = s;
    __syncthreads();

    if (g == 0) {
        float t = 0.f;
        #pragma unroll
        for (int m = 0; m < 8; ++m)
            t += sh[m * 32 + lane];
        g_ws[chunk * CHUNK_COLS + jj] = t;
    }

    if (chunk == NCHUNK - 1 && blockIdx.x == 0) {
        __syncthreads();
        float b = 0.f;
        #pragma unroll
        for (int i = threadIdx.x; i < OUT_F; i += 256)
            b += __ldg(&bias[i]);
        #pragma unroll
        for (int o = 16; o > 0; o >>= 1)
            b += __shfl_xor_sync(0xffffffffu, b, o);
        if (lane == 0) sh[g] = b;
        __syncthreads();
        if (threadIdx.x == 0) {
            float t = 0.f;
            #pragma unroll
            for (int m = 0; m < 8; ++m) t += sh[m];
            g_bsum = t;
        }
    }
}

// ---------------------------------------------------------------------------
// B (per chunk): partial dot of x[:, chunk] with ws[chunk]. One warp per row,
// 8 float4 iterations/lane, coalesced. Chunk 0 OVERWRITES out (graph-replay
// reset); later chunks accumulate; last chunk adds bias sum. Chunk order is
// enforced by stream order -> deterministic accumulation.
// ---------------------------------------------------------------------------
__global__ __launch_bounds__(256)
void rowdot_chunk(const float4* __restrict__ x4,
                  float* __restrict__ out, int chunk) {
    int gwarp = (blockIdx.x * blockDim.x + threadIdx.x) >> 5;
    int lane  = threadIdx.x & 31;
    if (gwarp >= BATCH) return;

    const float4* xr  = x4 + (size_t)gwarp * (IN_F / 4) + chunk * CHUNK_CG;
    const float4* ws4 = reinterpret_cast<const float4*>(g_ws) + chunk * CHUNK_CG;

    float acc = 0.f;
    #pragma unroll 8
    for (int i = lane; i < CHUNK_CG; i += 32) {
        float4 xv = xr[i];
        float4 wv = __ldg(&ws4[i]);
        acc += xv.x * wv.x + xv.y * wv.y + xv.z * wv.z + xv.w * wv.w;
    }
    #pragma unroll
    for (int o = 16; o > 0; o >>= 1)
        acc += __shfl_xor_sync(0xffffffffu, acc, o);

    if (lane == 0) {
        if (chunk == 0)
            out[gwarp] = acc;
        else if (chunk == NCHUNK - 1)
            out[gwarp] += acc + g_bsum;
        else
            out[gwarp] += acc;
    }
}

extern "C" void kernel_launch(void* const* d_in, const int* in_sizes, int n_in,
                              void* d_out, int out_size) {
    const float* x    = (const float*)d_in[0];   // [BATCH, IN_F]
    const float* W    = (const float*)d_in[1];   // [OUT_F, IN_F]
    const float* bias = (const float*)d_in[2];   // [OUT_F]
    float* out = (float*)d_out;                  // [BATCH, 1]
    (void)in_sizes; (void)n_in; (void)out_size;

    // Side stream + events, created once on the first (correctness) call —
    // handles only, no device memory. The same launch/record/wait sequence is
    // issued on every call, so device work is identical each time.
    static cudaStream_t s2 = nullptr;
    static cudaEvent_t  evFork;
    static cudaEvent_t  evChunk[NCHUNK];
    if (s2 == nullptr) {
        cudaStreamCreateWithFlags(&s2, cudaStreamNonBlocking);
        cudaEventCreateWithFlags(&evFork, cudaEventDisableTiming);
        for (int c = 0; c < NCHUNK; ++c)
            cudaEventCreateWithFlags(&evChunk[c], cudaEventDisableTiming);
    }

    const float4* W4 = reinterpret_cast<const float4*>(W);
    const float4* x4 = reinterpret_cast<const float4*>(x);

    // Fork: s2 joins the capture via the fork event.
    cudaEventRecord(evFork, 0);
    cudaStreamWaitEvent(s2, evFork, 0);

    // W-colsum pipeline on s2: per chunk, partial + finalize, then signal.
    for (int c = 0; c < NCHUNK; ++c) {
        wsum_partial_chunk<<<(NSPLIT_C * CHUNK_CG) / 256, 256, 0, s2>>>(W4, c);
        wsum_finalize_chunk<<<CHUNK_COLS / 32, 256, 0, s2>>>(bias, c);
        cudaEventRecord(evChunk[c], s2);
    }

    // rowdot pipeline on the capture (default) stream, gated per chunk.
    for (int c = 0; c < NCHUNK; ++c) {
        cudaStreamWaitEvent(0, evChunk[c], 0);
        rowdot_chunk<<<(BATCH * 32) / 256, 256>>>(x4, out, c);
    }
    // Final node waits evChunk[NCHUNK-1] -> all s2 work joins before capture end.
}

// round 12
// speedup vs baseline: 1.1650x; 1.1650x over previous
#include <cuda_runtime.h>

#define IN_F   4096
#define OUT_F  4096
#define BATCH  16384

#define NCHUNK     2
#define CHUNK_CG   512                 // float4 col-groups per chunk (2048 cols)
#define NSPLIT     256                 // row splits
#define ROWS_PS    (OUT_F / NSPLIT)    // 16 rows per split
#define WGRID      512                 // blocks per W-chunk kernel (2 per split)
#define FIN_BLOCKS 8                   // finalizer blocks per chunk

// Scratch (no device allocation) — overwritten every launch sequence.
__device__ float4 g_partial4[NCHUNK * NSPLIT * CHUNK_CG];  // 4 MB
__device__ float  g_ws[IN_F];
__device__ float  g_bsum;
__device__ int    g_ctr[NCHUNK];       // zero-init at load; reset by rowdot

// ---------------------------------------------------------------------------
// W chunk kernel: partial column sums + in-kernel deterministic finalize.
// Phase 1 (all 512 blocks): block b -> split = b>>1, colg = (b&1)*256 + t.
//   Coalesced float4 reads of 16 rows, unroll 4 (MLP_p1 cap per R6 finding).
//   Write partial, threadfence, count arrival.
// Phase 2 (blocks 0..7 only): spin until all 512 arrived (all blocks are
//   co-resident -> safe), then finalizer f sums colgroups [f*64, f*64+64)
//   over all 256 splits in FIXED order -> deterministic. Block 7 of the
//   last chunk also reduces bias -> g_bsum.
// ---------------------------------------------------------------------------
__global__ __launch_bounds__(256)
void wsum_chunk_kernel(const float4* __restrict__ W4,
                       const float* __restrict__ bias, int chunk) {
    const int t     = threadIdx.x;
    const int split = blockIdx.x >> 1;
    const int colg  = ((blockIdx.x & 1) << 8) | t;           // 0..511
    const int rowcg = IN_F / 4;                              // 1024

    const float4* p = W4 + (size_t)(split * ROWS_PS) * rowcg
                         + chunk * CHUNK_CG + colg;
    float4 acc = make_float4(0.f, 0.f, 0.f, 0.f);
    #pragma unroll 4
    for (int r = 0; r < ROWS_PS; ++r) {
        float4 v = p[(size_t)r * rowcg];
        acc.x += v.x; acc.y += v.y; acc.z += v.z; acc.w += v.w;
    }
    g_partial4[(chunk << 17) + (split << 9) + colg] = acc;   // chunk*131072+split*512
    __threadfence();
    __syncthreads();
    if (t == 0) atomicAdd(&g_ctr[chunk], 1);

    if (blockIdx.x < FIN_BLOCKS) {
        // Wait for all 512 partial writers of this chunk.
        if (t == 0) {
            while (*(volatile int*)&g_ctr[chunk] < WGRID) { }
        }
        __syncthreads();
        __threadfence();

        __shared__ float4 sub[256];
        const int cg = (blockIdx.x << 6) + (t & 63);         // colgroup
        const int sg = t >> 6;                               // split-group 0..3
        float4 a = make_float4(0.f, 0.f, 0.f, 0.f);
        #pragma unroll 8
        for (int s = sg * 64; s < sg * 64 + 64; ++s) {
            float4 v = g_partial4[(chunk << 17) + (s << 9) + cg];
            a.x += v.x; a.y += v.y; a.z += v.z; a.w += v.w;
        }
        sub[t] = a;
        __syncthreads();
        if (t < 64) {
            float4 r0 = sub[t], r1 = sub[64 + t], r2 = sub[128 + t], r3 = sub[192 + t];
            float4 w;
            w.x = r0.x + r1.x + r2.x + r3.x;
            w.y = r0.y + r1.y + r2.y + r3.y;
            w.z = r0.z + r1.z + r2.z + r3.z;
            w.w = r0.w + r1.w + r2.w + r3.w;
            reinterpret_cast<float4*>(g_ws)[(chunk << 9) + (blockIdx.x << 6) + t] = w;
        }

        // Bias sum on the last chunk's last finalizer block.
        if (chunk == NCHUNK - 1 && blockIdx.x == FIN_BLOCKS - 1) {
            __syncthreads();
            float b = 0.f;
            #pragma unroll
            for (int i = t; i < OUT_F; i += 256)
                b += __ldg(&bias[i]);
            #pragma unroll
            for (int o = 16; o > 0; o >>= 1)
                b += __shfl_xor_sync(0xffffffffu, b, o);
            __shared__ float shb[8];
            if ((t & 31) == 0) shb[t >> 5] = b;
            __syncthreads();
            if (t == 0) {
                float s = 0.f;
                #pragma unroll
                for (int m = 0; m < 8; ++m) s += shb[m];
                g_bsum = s;
            }
        }
    }
}

// ---------------------------------------------------------------------------
// rowdot chunk: partial dot of x[:, chunk cols] with ws chunk. One warp/row,
// 16 float4 iters/lane (unroll 8), coalesced. Chunk 0 overwrites out
// (replay reset); chunk 1 accumulates + bias. Also resets this chunk's
// arrival counter for the next replay (runs strictly after W-chunk via event,
// strictly before next replay's W-chunk via graph order).
// ---------------------------------------------------------------------------
__global__ __launch_bounds__(256)
void rowdot_chunk(const float4* __restrict__ x4,
                  float* __restrict__ out, int chunk) {
    if (blockIdx.x == 0 && threadIdx.x == 0) g_ctr[chunk] = 0;

    int gwarp = (blockIdx.x * blockDim.x + threadIdx.x) >> 5;  // 0..16383 exactly
    int lane  = threadIdx.x & 31;

    const float4* xr  = x4 + (size_t)gwarp * (IN_F / 4) + chunk * CHUNK_CG;
    const float4* ws4 = reinterpret_cast<const float4*>(g_ws) + chunk * CHUNK_CG;

    float acc = 0.f;
    #pragma unroll 8
    for (int i = lane; i < CHUNK_CG; i += 32) {
        float4 xv = xr[i];
        float4 wv = __ldg(&ws4[i]);
        acc += xv.x * wv.x + xv.y * wv.y + xv.z * wv.z + xv.w * wv.w;
    }
    #pragma unroll
    for (int o = 16; o > 0; o >>= 1)
        acc += __shfl_xor_sync(0xffffffffu, acc, o);

    if (lane == 0) {
        if (chunk == 0) out[gwarp] = acc;
        else            out[gwarp] += acc + g_bsum;
    }
}

extern "C" void kernel_launch(void* const* d_in, const int* in_sizes, int n_in,
                              void* d_out, int out_size) {
    const float* x    = (const float*)d_in[0];   // [BATCH, IN_F]
    const float* W    = (const float*)d_in[1];   // [OUT_F, IN_F]
    const float* bias = (const float*)d_in[2];   // [OUT_F]
    float* out = (float*)d_out;                  // [BATCH, 1]
    (void)in_sizes; (void)n_in; (void)out_size;

    // Handles only (no device memory), created once; identical launch
    // sequence every call -> deterministic, graph-capturable.
    static cudaStream_t s2 = nullptr;
    static cudaEvent_t  evFork, evChunk[NCHUNK];
    if (s2 == nullptr) {
        cudaStreamCreateWithFlags(&s2, cudaStreamNonBlocking);
        cudaEventCreateWithFlags(&evFork, cudaEventDisableTiming);
        for (int c = 0; c < NCHUNK; ++c)
            cudaEventCreateWithFlags(&evChunk[c], cudaEventDisableTiming);
    }

    const float4* W4 = reinterpret_cast<const float4*>(W);
    const float4* x4 = reinterpret_cast<const float4*>(x);

    // Fork side stream into the capture.
    cudaEventRecord(evFork, 0);
    cudaStreamWaitEvent(s2, evFork, 0);

    // Producer: one fused W kernel per chunk on s2.
    for (int c = 0; c < NCHUNK; ++c) {
        wsum_chunk_kernel<<<WGRID, 256, 0, s2>>>(W4, bias, c);
        cudaEventRecord(evChunk[c], s2);
    }

    // Consumer: rowdot chunks on the capture stream, gated per chunk.
    for (int c = 0; c < NCHUNK; ++c) {
        cudaStreamWaitEvent(0, evChunk[c], 0);
        rowdot_chunk<<<(BATCH * 32) / 256, 256>>>(x4, out, c);
    }
}

// round 13
// speedup vs baseline: 1.2124x; 1.0407x over previous
#include <cuda_runtime.h>

#define IN_F   4096
#define OUT_F  4096
#define BATCH  16384

#define NSPLIT     256                 // row splits for W partials
#define ROWS_PS    (OUT_F / NSPLIT)    // 16 rows per split
#define ROWCG      (IN_F / 4)          // 1024 float4 per W row
#define WGRID      1024                // 4 blocks per split
#define FIN_BLOCKS 16                  // finalizer blocks (64 colgroups each)

// Scratch (no device allocation) — overwritten every launch sequence.
__device__ float4 g_partial4[NSPLIT * ROWCG];   // 4 MB (L2-resident)
__device__ float  g_ws[IN_F];
__device__ float  g_bsum;
__device__ int    g_ctr;               // zero-init at load; reset by rowdot

// ---------------------------------------------------------------------------
// Fused W kernel: partial column sums + in-kernel deterministic finalize.
// Phase 1 (all 1024 blocks): block b -> split = b>>2, colg = (b&3)*256 + t.
//   Coalesced float4 streaming reads (__ldcs) of 16 rows, unroll 4
//   (MLP_p1 cap, R6 finding). Write partial, fence, count arrival.
//   All 1024 blocks are co-resident (8 blocks/SM x 148 SMs = 1184) -> the
//   finalizer spin below cannot deadlock.
// Phase 2 (blocks 0..15): spin until all 1024 arrived, then finalizer f
//   sums colgroups [f*64, f*64+64) over all 256 splits in FIXED order
//   (4 split-groups x 64, smem cross-reduce) -> deterministic.
//   Block 15 also reduces bias -> g_bsum.
// ---------------------------------------------------------------------------
__global__ __launch_bounds__(256)
void wsum_fused_kernel(const float4* __restrict__ W4,
                       const float* __restrict__ bias) {
    const int t     = threadIdx.x;
    const int split = blockIdx.x >> 2;
    const int colg  = ((blockIdx.x & 3) << 8) | t;           // 0..1023

    const float4* p = W4 + (size_t)(split * ROWS_PS) * ROWCG + colg;
    float4 acc = make_float4(0.f, 0.f, 0.f, 0.f);
    #pragma unroll 4
    for (int r = 0; r < ROWS_PS; ++r) {
        float4 v = __ldcs(&p[(size_t)r * ROWCG]);
        acc.x += v.x; acc.y += v.y; acc.z += v.z; acc.w += v.w;
    }
    g_partial4[(split << 10) + colg] = acc;
    __threadfence();
    __syncthreads();
    if (t == 0) atomicAdd(&g_ctr, 1);

    if (blockIdx.x < FIN_BLOCKS) {
        if (t == 0) {
            while (*(volatile int*)&g_ctr < WGRID) { }
        }
        __syncthreads();
        __threadfence();

        __shared__ float4 sub[256];
        const int cg = (blockIdx.x << 6) + (t & 63);         // colgroup 0..1023
        const int sg = t >> 6;                               // split-group 0..3
        float4 a = make_float4(0.f, 0.f, 0.f, 0.f);
        #pragma unroll 8
        for (int s = sg * 64; s < sg * 64 + 64; ++s) {
            float4 v = g_partial4[(s << 10) + cg];
            a.x += v.x; a.y += v.y; a.z += v.z; a.w += v.w;
        }
        sub[t] = a;
        __syncthreads();
        if (t < 64) {
            float4 r0 = sub[t], r1 = sub[64 + t], r2 = sub[128 + t], r3 = sub[192 + t];
            float4 w;
            w.x = r0.x + r1.x + r2.x + r3.x;
            w.y = r0.y + r1.y + r2.y + r3.y;
            w.z = r0.z + r1.z + r2.z + r3.z;
            w.w = r0.w + r1.w + r2.w + r3.w;
            reinterpret_cast<float4*>(g_ws)[(blockIdx.x << 6) + t] = w;
        }

        if (blockIdx.x == FIN_BLOCKS - 1) {
            __syncthreads();
            float b = 0.f;
            #pragma unroll
            for (int i = t; i < OUT_F; i += 256)
                b += __ldg(&bias[i]);
            #pragma unroll
            for (int o = 16; o > 0; o >>= 1)
                b += __shfl_xor_sync(0xffffffffu, b, o);
            __shared__ float shb[8];
            if ((t & 31) == 0) shb[t >> 5] = b;
            __syncthreads();
            if (t == 0) {
                float s = 0.f;
                #pragma unroll
                for (int m = 0; m < 8; ++m) s += shb[m];
                g_bsum = s;
            }
        }
    }
}

// ---------------------------------------------------------------------------
// rowdot: out[row] = dot(x[row], ws) + bsum. One warp per row, 32 float4
// iters/lane, coalesced; x streamed with __ldcs (no reuse), ws via __ldg
// (L1-resident). unroll 4 (MLP_p1 cap, mirrors the R6 A1 improvement).
// Fixed shuffle-reduce order -> deterministic. Also resets g_ctr for the
// next graph replay (runs strictly after wsum in stream order).
// ---------------------------------------------------------------------------
__global__ __launch_bounds__(256)
void rowdot_kernel(const float4* __restrict__ x4,
                   float* __restrict__ out) {
    if (blockIdx.x == 0 && threadIdx.x == 0) g_ctr = 0;

    int gwarp = (blockIdx.x * blockDim.x + threadIdx.x) >> 5;  // 0..16383
    int lane  = threadIdx.x & 31;

    const float4* xr  = x4 + (size_t)gwarp * ROWCG;
    const float4* ws4 = reinterpret_cast<const float4*>(g_ws);

    float acc = 0.f;
    #pragma unroll 4
    for (int i = lane; i < ROWCG; i += 32) {
        float4 xv = __ldcs(&xr[i]);
        float4 wv = __ldg(&ws4[i]);
        acc += xv.x * wv.x + xv.y * wv.y + xv.z * wv.z + xv.w * wv.w;
    }
    #pragma unroll
    for (int o = 16; o > 0; o >>= 1)
        acc += __shfl_xor_sync(0xffffffffu, acc, o);
    if (lane == 0)
        out[gwarp] = acc + g_bsum;
}

extern "C" void kernel_launch(void* const* d_in, const int* in_sizes, int n_in,
                              void* d_out, int out_size) {
    const float* x    = (const float*)d_in[0];   // [BATCH, IN_F]
    const float* W    = (const float*)d_in[1];   // [OUT_F, IN_F]
    const float* bias = (const float*)d_in[2];   // [OUT_F]
    float* out = (float*)d_out;                  // [BATCH, 1]
    (void)in_sizes; (void)n_in; (void)out_size;

    // Serial, two kernels, one stream — DRAM-bound phases don't overlap
    // profitably (measured R9/R12), so minimize gaps instead.
    wsum_fused_kernel<<<WGRID, 256>>>(
        reinterpret_cast<const float4*>(W), bias);

    rowdot_kernel<<<(BATCH * 32) / 256, 256>>>(
        reinterpret_cast<const float4*>(x), out);
}

// round 14
// speedup vs baseline: 1.3239x; 1.0919x over previous
#include <cuda_runtime.h>

#define IN_F   4096
#define OUT_F  4096
#define BATCH  16384

#define NSPLIT   256                  // row splits for W partials
#define ROWS_PS  (OUT_F / NSPLIT)     // 16 rows per split
#define ROWCG    (IN_F / 4)           // 1024 float4 per W row
#define WGRID    1024                 // 4 blocks per split

// Scratch (no device allocation) — overwritten every launch sequence.
__device__ float4 g_partial4[NSPLIT * ROWCG];   // 4 MB (L2-resident)
__device__ float  g_ws[IN_F];
__device__ float  g_bsum;

// ---------------------------------------------------------------------------
// A1: partial column sums of W (exact R8 structure — measured 13.5us @63.5%).
// block b -> split = b>>2, colg = (b&3)*256 + t. Coalesced float4 reads of
// 16 rows, unroll 4. Plain loads (the R13 __ldcs variant regressed).
// ---------------------------------------------------------------------------
__global__ __launch_bounds__(256)
void wsum_partial_kernel(const float4* __restrict__ W4) {
    const int t     = threadIdx.x;
    const int split = blockIdx.x >> 2;
    const int colg  = ((blockIdx.x & 3) << 8) | t;           // 0..1023

    const float4* p = W4 + (size_t)(split * ROWS_PS) * ROWCG + colg;
    float4 acc = make_float4(0.f, 0.f, 0.f, 0.f);
    #pragma unroll 4
    for (int r = 0; r < ROWS_PS; ++r) {
        float4 v = p[(size_t)r * ROWCG];
        acc.x += v.x; acc.y += v.y; acc.z += v.z; acc.w += v.w;
    }
    g_partial4[(split << 10) + colg] = acc;
}

// ---------------------------------------------------------------------------
// A2: finalize ws + bias. 128 blocks x 256. PDL: syncs on A1 completion at
// entry, so its launch latency hides under A1's tail.
// Thread (c = t>>5, lane): block b owns colgroups [b*8, b*8+8); sums splits
// {lane, lane+32, ..., lane+224} (8 float4 loads, unroll 8, L2-resident),
// then shuffle-xor reduces the 32 lanes per component (fixed order ->
// deterministic). Lane 0 writes ws float4. Block 0 also reduces bias.
// ---------------------------------------------------------------------------
__global__ __launch_bounds__(256)
void wsum_finalize_kernel(const float* __restrict__ bias) {
    cudaGridDependencySynchronize();   // wait for A1 (PDL)

    const int t    = threadIdx.x;
    const int lane = t & 31;
    const int c    = t >> 5;                                  // 0..7
    const int cg   = (blockIdx.x << 3) + c;                   // colgroup 0..1023

    float4 a = make_float4(0.f, 0.f, 0.f, 0.f);
    #pragma unroll 8
    for (int k = 0; k < 8; ++k) {
        float4 v = g_partial4[((lane + (k << 5)) << 10) + cg];
        a.x += v.x; a.y += v.y; a.z += v.z; a.w += v.w;
    }
    #pragma unroll
    for (int o = 16; o > 0; o >>= 1) {
        a.x += __shfl_xor_sync(0xffffffffu, a.x, o);
        a.y += __shfl_xor_sync(0xffffffffu, a.y, o);
        a.z += __shfl_xor_sync(0xffffffffu, a.z, o);
        a.w += __shfl_xor_sync(0xffffffffu, a.w, o);
    }
    if (lane == 0)
        reinterpret_cast<float4*>(g_ws)[cg] = a;

    if (blockIdx.x == 0) {
        __syncthreads();
        float b = 0.f;
        #pragma unroll
        for (int i = t; i < OUT_F; i += 256)
            b += __ldg(&bias[i]);
        #pragma unroll
        for (int o = 16; o > 0; o >>= 1)
            b += __shfl_xor_sync(0xffffffffu, b, o);
        __shared__ float shb[8];
        if (lane == 0) shb[t >> 5] = b;
        __syncthreads();
        if (t == 0) {
            float s = 0.f;
            #pragma unroll
            for (int m = 0; m < 8; ++m) s += shb[m];
            g_bsum = s;
        }
    }
}

// ---------------------------------------------------------------------------
// B: out[row] = dot(x[row], ws) + bsum. One warp per row — exact R3 loop
// (measured 44.6us @77% DRAM). PDL: prefetch 4 float4 of x per lane FIRST,
// then grid-dependency-sync (waits for A2), then consume. The x DRAM stream
// starts during A2's tail; launch gap disappears. Fixed accumulation order
// -> deterministic.
// ---------------------------------------------------------------------------
__global__ __launch_bounds__(256)
void rowdot_kernel(const float4* __restrict__ x4,
                   float* __restrict__ out) {
    int gwarp = (blockIdx.x * blockDim.x + threadIdx.x) >> 5;  // 0..16383
    int lane  = threadIdx.x & 31;

    const float4* xr = x4 + (size_t)gwarp * ROWCG;
    float4 p0 = xr[lane];
    float4 p1 = xr[lane + 32];
    float4 p2 = xr[lane + 64];
    float4 p3 = xr[lane + 96];

    cudaGridDependencySynchronize();   // ws/bsum ready (PDL)

    const float4* ws4 = reinterpret_cast<const float4*>(g_ws);
    float4 w0 = __ldg(&ws4[lane]);
    float4 w1 = __ldg(&ws4[lane + 32]);
    float4 w2 = __ldg(&ws4[lane + 64]);
    float4 w3 = __ldg(&ws4[lane + 96]);

    float acc = p0.x * w0.x + p0.y * w0.y + p0.z * w0.z + p0.w * w0.w;
    acc      += p1.x * w1.x + p1.y * w1.y + p1.z * w1.z + p1.w * w1.w;
    acc      += p2.x * w2.x + p2.y * w2.y + p2.z * w2.z + p2.w * w2.w;
    acc      += p3.x * w3.x + p3.y * w3.y + p3.z * w3.z + p3.w * w3.w;

    #pragma unroll 8
    for (int i = lane + 128; i < ROWCG; i += 32) {
        float4 xv = xr[i];
        float4 wv = __ldg(&ws4[i]);
        acc += xv.x * wv.x + xv.y * wv.y + xv.z * wv.z + xv.w * wv.w;
    }
    #pragma unroll
    for (int o = 16; o > 0; o >>= 1)
        acc += __shfl_xor_sync(0xffffffffu, acc, o);
    if (lane == 0)
        out[gwarp] = acc + g_bsum;
}

extern "C" void kernel_launch(void* const* d_in, const int* in_sizes, int n_in,
                              void* d_out, int out_size) {
    const float* x    = (const float*)d_in[0];   // [BATCH, IN_F]
    const float* W    = (const float*)d_in[1];   // [OUT_F, IN_F]
    const float* bias = (const float*)d_in[2];   // [OUT_F]
    float* out = (float*)d_out;                  // [BATCH, 1]
    (void)in_sizes; (void)n_in; (void)out_size;

    // A1: plain launch.
    wsum_partial_kernel<<<WGRID, 256>>>(reinterpret_cast<const float4*>(W));

    // A2 + rowdot launched with programmatic dependent launch so their
    // prologues overlap the predecessor's tail; cudaGridDependencySynchronize
    // inside each kernel enforces correctness. Same sequence every call ->
    // deterministic, graph-capturable (programmatic edges).
    cudaLaunchAttribute attr[1];
    attr[0].id = cudaLaunchAttributeProgrammaticStreamSerialization;
    attr[0].val.programmaticStreamSerializationAllowed = 1;

    {
        cudaLaunchConfig_t cfg = {};
        cfg.gridDim  = dim3(IN_F / 32, 1, 1);    // 128 blocks
        cfg.blockDim = dim3(256, 1, 1);
        cfg.stream   = 0;
        cfg.attrs    = attr;
        cfg.numAttrs = 1;
        cudaLaunchKernelEx(&cfg, wsum_finalize_kernel, bias);
    }
    {
        cudaLaunchConfig_t cfg = {};
        cfg.gridDim  = dim3((BATCH * 32) / 256, 1, 1);  // 2048 blocks
        cfg.blockDim = dim3(256, 1, 1);
        cfg.stream   = 0;
        cfg.attrs    = attr;
        cfg.numAttrs = 1;
        cudaLaunchKernelEx(&cfg, rowdot_kernel,
                           reinterpret_cast<const float4*>(x), out);
    }
}